// round 4
// baseline (speedup 1.0000x reference)
#include <cuda_runtime.h>

#define BATCH 4
#define SEQ   1370
#define NH    16
#define HD    64
#define HID   1024
#define NTOK  (BATCH * SEQ)   // 5480

// Scratch for projected Q/K/V in [B, NH, L, HD] layout (22.4 MB each).
__device__ float g_q[(size_t)BATCH * NH * SEQ * HD];
__device__ float g_k[(size_t)BATCH * NH * SEQ * HD];
__device__ float g_v[(size_t)BATCH * NH * SEQ * HD];

// ---------------------------------------------------------------------------
// Phase 1: fused QKV projection.  Y = X @ W^T + b for Wq/Wk/Wv, written
// directly into [B, NH, L, HD] layout. Classic smem-tiled SGEMM:
// BM=128 tokens x BN=128 out-channels x BK=16, 256 threads, 8x8 microtile
// (split as 2x 4-row / 4-col groups 64 apart to keep LDS conflicts ~2-way).
// ---------------------------------------------------------------------------
#define BM   128
#define BN   128
#define BKK  16
#define APAD 132   // row stride pad: breaks STS transpose conflicts

__global__ __launch_bounds__(256, 2)
void qkv_gemm(const float* __restrict__ X,
              const float* __restrict__ Wq, const float* __restrict__ bq,
              const float* __restrict__ Wk, const float* __restrict__ bk,
              const float* __restrict__ Wv, const float* __restrict__ bv)
{
    __shared__ float As[BKK][APAD];
    __shared__ float Bs[BKK][APAD];

    const int m0    = blockIdx.x * BM;
    const int ncol0 = blockIdx.y * BN;       // 0..3071, 1024-aligned per projection
    const int proj  = ncol0 >> 10;           // 0=q, 1=k, 2=v
    const int o0    = ncol0 & 1023;

    const float* W    = (proj == 0) ? Wq : (proj == 1) ? Wk : Wv;
    const float* bias = (proj == 0) ? bq : (proj == 1) ? bk : bv;
    float*       dst  = (proj == 0) ? g_q : (proj == 1) ? g_k : g_v;

    const int tid = threadIdx.x;
    const int tx  = tid & 15;
    const int ty  = tid >> 4;

    float acc[8][8];
    #pragma unroll
    for (int i = 0; i < 8; i++)
        #pragma unroll
        for (int j = 0; j < 8; j++) acc[i][j] = 0.f;

    for (int k0 = 0; k0 < HID; k0 += BKK) {
        // g2s: 128 rows x 16 k, transposed into As[k][m] / Bs[k][n].
        #pragma unroll
        for (int i = 0; i < 2; i++) {
            int f   = i * 256 + tid;       // float4 id in [0, 512)
            int row = f >> 2;              // 0..127
            int kk  = (f & 3) << 2;        // 0,4,8,12
            int gm  = m0 + row;
            float4 va = (gm < NTOK)
                ? *(const float4*)(X + (size_t)gm * HID + k0 + kk)
                : make_float4(0.f, 0.f, 0.f, 0.f);
            As[kk + 0][row] = va.x; As[kk + 1][row] = va.y;
            As[kk + 2][row] = va.z; As[kk + 3][row] = va.w;
            float4 vb = *(const float4*)(W + (size_t)(o0 + row) * HID + k0 + kk);
            Bs[kk + 0][row] = vb.x; Bs[kk + 1][row] = vb.y;
            Bs[kk + 2][row] = vb.z; Bs[kk + 3][row] = vb.w;
        }
        __syncthreads();

        #pragma unroll
        for (int kk = 0; kk < BKK; kk++) {
            float a[8], b[8];
            #pragma unroll
            for (int j = 0; j < 4; j++) {
                a[j]     = As[kk][ty * 4 + j];
                a[j + 4] = As[kk][64 + ty * 4 + j];
                b[j]     = Bs[kk][tx * 4 + j];
                b[j + 4] = Bs[kk][64 + tx * 4 + j];
            }
            #pragma unroll
            for (int i = 0; i < 8; i++)
                #pragma unroll
                for (int j = 0; j < 8; j++)
                    acc[i][j] += a[i] * b[j];
        }
        __syncthreads();
    }

    // Epilogue: add bias, scatter into [B, NH, L, HD].
    #pragma unroll
    for (int i = 0; i < 8; i++) {
        int r  = (i < 4) ? (ty * 4 + i) : (64 + ty * 4 + (i - 4));
        int gm = m0 + r;
        if (gm >= NTOK) continue;
        int bb = gm / SEQ;
        int ll = gm - bb * SEQ;
        #pragma unroll
        for (int j = 0; j < 8; j++) {
            int c = (j < 4) ? (tx * 4 + j) : (64 + tx * 4 + (j - 4));
            int o = o0 + c;
            float y = acc[i][j] + bias[o];
            int head = o >> 6;
            int dd   = o & 63;
            dst[(((size_t)bb * NH + head) * SEQ + ll) * HD + dd] = y;
        }
    }
}

// ---------------------------------------------------------------------------
// Phase 2: flash attention, fp32. One block per (q-tile, b*h).
// BQ=64 x BKV=64 tiles, 256 threads = 16x16, 4x4 microtile.
// Smem: Qs + (K/P union) + Vs = exactly 48 KB via an XOR swizzle
// (no padding, float4-friendly, breaks 16-way column-read conflicts to 2-way).
// ---------------------------------------------------------------------------
#define BQ  64
#define BKV 64

__device__ __forceinline__ int swz(int r, int c) {
    // element (r, c) of a 64x64 tile; c in [0,64). (r & 28) = ((r>>2)&7)<<2.
    return r * 64 + (c ^ (r & 28));
}

__global__ __launch_bounds__(256, 2)
void flash_attn(float* __restrict__ out)
{
    __shared__ float Qs [BQ  * 64];
    __shared__ float KPs[BKV * 64];   // K tile; reused as P tile after S is built
    __shared__ float Vs [BKV * 64];

    const int qt    = blockIdx.x;        // 0..21
    const int bh    = blockIdx.y;        // 0..63
    const int batch = bh >> 4;
    const int head  = bh & 15;
    const float* Q = g_q + (size_t)bh * SEQ * HD;
    const float* K = g_k + (size_t)bh * SEQ * HD;
    const float* V = g_v + (size_t)bh * SEQ * HD;
    const int q0 = qt * BQ;

    const int tid = threadIdx.x;
    const int tx  = tid & 15;
    const int ty  = tid >> 4;

    // Load Q tile (zero-fill padded rows).
    #pragma unroll
    for (int i = 0; i < 4; i++) {
        int f   = i * 256 + tid;      // float4 id in [0, 1024)
        int row = f >> 4;             // 0..63
        int c4  = (f & 15) << 2;      // 0..60
        int gq  = q0 + row;
        float4 v = (gq < SEQ)
            ? *(const float4*)(Q + (size_t)gq * HD + c4)
            : make_float4(0.f, 0.f, 0.f, 0.f);
        *(float4*)(&Qs[swz(row, c4)]) = v;   // (c4^g)+k == (c4+k)^g for k<4
    }

    float m_[4], l_[4], O[4][4];
    #pragma unroll
    for (int i = 0; i < 4; i++) {
        m_[i] = -1e30f;
        l_[i] = 0.f;
        #pragma unroll
        for (int j = 0; j < 4; j++) O[i][j] = 0.f;
    }

    for (int k0 = 0; k0 < SEQ; k0 += BKV) {
        __syncthreads();   // prior PV readers done before overwriting KPs/Vs

        // Load K and V tiles (zero-fill padded rows).
        #pragma unroll
        for (int i = 0; i < 4; i++) {
            int f   = i * 256 + tid;
            int row = f >> 4;
            int c4  = (f & 15) << 2;
            int gk  = k0 + row;
            float4 vk, vv;
            if (gk < SEQ) {
                vk = *(const float4*)(K + (size_t)gk * HD + c4);
                vv = *(const float4*)(V + (size_t)gk * HD + c4);
            } else {
                vk = make_float4(0.f, 0.f, 0.f, 0.f);
                vv = vk;
            }
            int base = swz(row, c4);
            *(float4*)(&KPs[base]) = vk;
            *(float4*)(&Vs[base])  = vv;
        }
        __syncthreads();

        // S = Q @ K^T  (thread owns q rows ty*4.., k cols tx*4..)
        float S[4][4];
        #pragma unroll
        for (int i = 0; i < 4; i++)
            #pragma unroll
            for (int j = 0; j < 4; j++) S[i][j] = 0.f;

        #pragma unroll 8
        for (int kd = 0; kd < 64; kd++) {
            float qa[4], kb[4];
            #pragma unroll
            for (int j = 0; j < 4; j++) {
                qa[j] = Qs [swz(ty * 4 + j, kd)];
                kb[j] = KPs[swz(tx * 4 + j, kd)];
            }
            #pragma unroll
            for (int i = 0; i < 4; i++)
                #pragma unroll
                for (int j = 0; j < 4; j++)
                    S[i][j] += qa[i] * kb[j];
        }

        // scale + key mask
        #pragma unroll
        for (int i = 0; i < 4; i++)
            #pragma unroll
            for (int j = 0; j < 4; j++) {
                float s = S[i][j] * 0.125f;   // 1/sqrt(64)
                if (k0 + tx * 4 + j >= SEQ) s = -1e30f;
                S[i][j] = s;
            }

        // Online softmax. Row group = 16 lanes of same ty; lane = (ty&1)*16+tx,
        // so xor offsets {8,4,2,1} stay inside each 16-lane half-warp.
        #pragma unroll
        for (int i = 0; i < 4; i++) {
            float r = fmaxf(fmaxf(S[i][0], S[i][1]), fmaxf(S[i][2], S[i][3]));
            #pragma unroll
            for (int off = 8; off > 0; off >>= 1)
                r = fmaxf(r, __shfl_xor_sync(0xffffffffu, r, off));
            float mnew  = fmaxf(m_[i], r);
            float alpha = __expf(m_[i] - mnew);
            float rs = 0.f;
            #pragma unroll
            for (int j = 0; j < 4; j++) {
                float p = __expf(S[i][j] - mnew);
                S[i][j] = p;
                rs += p;
            }
            #pragma unroll
            for (int off = 8; off > 0; off >>= 1)
                rs += __shfl_xor_sync(0xffffffffu, rs, off);
            l_[i] = l_[i] * alpha + rs;
            m_[i] = mnew;
            #pragma unroll
            for (int j = 0; j < 4; j++) O[i][j] *= alpha;
        }

        __syncthreads();   // all K reads done; reuse KPs as P
        #pragma unroll
        for (int i = 0; i < 4; i++)
            #pragma unroll
            for (int j = 0; j < 4; j++)
                KPs[swz(ty * 4 + i, tx * 4 + j)] = S[i][j];
        __syncthreads();

        // O += P @ V  (thread owns q rows ty*4.., d cols tx*4..)
        #pragma unroll 8
        for (int kc = 0; kc < 64; kc++) {
            float pa[4], vb[4];
            #pragma unroll
            for (int j = 0; j < 4; j++) {
                pa[j] = KPs[swz(ty * 4 + j, kc)];
                vb[j] = Vs [swz(kc, tx * 4 + j)];
            }
            #pragma unroll
            for (int i = 0; i < 4; i++)
                #pragma unroll
                for (int j = 0; j < 4; j++)
                    O[i][j] += pa[i] * vb[j];
        }
    }

    // Epilogue: normalize and write ctx[b, l, head*64 + d].
    #pragma unroll
    for (int i = 0; i < 4; i++) {
        int gq = q0 + ty * 4 + i;
        if (gq >= SEQ) continue;
        float inv = 1.f / l_[i];
        #pragma unroll
        for (int j = 0; j < 4; j++) {
            out[((size_t)batch * SEQ + gq) * HID + head * HD + tx * 4 + j] =
                O[i][j] * inv;
        }
    }
}

// ---------------------------------------------------------------------------
// Launch
// ---------------------------------------------------------------------------
extern "C" void kernel_launch(void* const* d_in, const int* in_sizes, int n_in,
                              void* d_out, int out_size)
{
    const float* X  = (const float*)d_in[0];
    const float* Wq = (const float*)d_in[1];
    const float* bq = (const float*)d_in[2];
    const float* Wk = (const float*)d_in[3];
    const float* bk = (const float*)d_in[4];
    const float* Wv = (const float*)d_in[5];
    const float* bv = (const float*)d_in[6];
    float* out = (float*)d_out;

    dim3 g1((NTOK + BM - 1) / BM, (3 * HID) / BN);   // 43 x 24
    qkv_gemm<<<g1, 256>>>(X, Wq, bq, Wk, bk, Wv, bv);

    dim3 g2((SEQ + BQ - 1) / BQ, BATCH * NH);        // 22 x 64
    flash_attn<<<g2, 256>>>(out);
}

// round 7
// speedup vs baseline: 1.7751x; 1.7751x over previous
#include <cuda_runtime.h>
#include <cuda_bf16.h>
#include <cstdint>

#define BATCH 4
#define SEQ   1370
#define NH    16
#define HD    64
#define HID   1024
#define NTOK  (BATCH * SEQ)   // 5480

// Scratch for projected Q/K/V in [B, NH, L, HD] layout.
__device__ float g_q[(size_t)BATCH * NH * SEQ * HD];
__device__ float g_k[(size_t)BATCH * NH * SEQ * HD];
__device__ float g_v[(size_t)BATCH * NH * SEQ * HD];

// ===========================================================================
// Helpers
// ===========================================================================
__device__ __forceinline__ uint32_t smem_u32(const void* p) {
    uint32_t a;
    asm("{ .reg .u64 t; cvta.to.shared.u64 t, %1; cvt.u32.u64 %0, t; }"
        : "=r"(a) : "l"(p));
    return a;
}

#define LDMX4(r, addr) \
    asm volatile("ldmatrix.sync.aligned.m8n8.x4.shared.b16 {%0,%1,%2,%3}, [%4];" \
        : "=r"((r)[0]), "=r"((r)[1]), "=r"((r)[2]), "=r"((r)[3]) : "r"(addr))

#define MMA16816(d, a, b0, b1) \
    asm volatile("mma.sync.aligned.m16n8k16.row.col.f32.bf16.bf16.f32 " \
        "{%0,%1,%2,%3}, {%4,%5,%6,%7}, {%8,%9}, {%0,%1,%2,%3};" \
        : "+f"((d)[0]), "+f"((d)[1]), "+f"((d)[2]), "+f"((d)[3]) \
        : "r"((a)[0]), "r"((a)[1]), "r"((a)[2]), "r"((a)[3]), "r"(b0), "r"(b1))

// fp32 -> (bf16 hi, bf16 lo) split, 4 elements, stored as 8B each plane.
__device__ __forceinline__ void split_sts(char* hp, char* lp, uint32_t off, float4 v) {
    __nv_bfloat16 h0 = __float2bfloat16_rn(v.x);
    __nv_bfloat16 h1 = __float2bfloat16_rn(v.y);
    __nv_bfloat16 h2 = __float2bfloat16_rn(v.z);
    __nv_bfloat16 h3 = __float2bfloat16_rn(v.w);
    float l0 = v.x - __bfloat162float(h0);
    float l1 = v.y - __bfloat162float(h1);
    float l2 = v.z - __bfloat162float(h2);
    float l3 = v.w - __bfloat162float(h3);
    __nv_bfloat162 hA = __halves2bfloat162(h0, h1);
    __nv_bfloat162 hB = __halves2bfloat162(h2, h3);
    uint32_t lA, lB;
    asm("cvt.rn.bf16x2.f32 %0, %1, %2;" : "=r"(lA) : "f"(l1), "f"(l0));
    asm("cvt.rn.bf16x2.f32 %0, %1, %2;" : "=r"(lB) : "f"(l3), "f"(l2));
    *(uint2*)(hp + off) = make_uint2(*(uint32_t*)&hA, *(uint32_t*)&hB);
    *(uint2*)(lp + off) = make_uint2(lA, lB);
}

// ===========================================================================
// Phase 1: QKV projection on mma.sync (bf16 hi/lo split, fp32 accum).
// C[5480, 3072] = X[5480,1024] @ W^T + b, scattered into g_q/g_k/g_v.
// Block tile 128x128, warp tile 32x64 (8 warps as 4m x 2n), BK=32,
// double-buffered smem with register-staged global loads.
// Y = Xh*Wh + Xh*Wl + Xl*Wh  (ll term dropped; error ~2^-18)
// ===========================================================================
#define QBK     32
#define QROWB   80                   // smem row stride bytes (64B data + 16B pad)
#define QTILE   (128 * QROWB)        // 10240 B per matrix plane
#define QBUF    (4 * QTILE)          // Ah | Al | Bh | Bl = 40960 B
#define QK_SMEM (2 * QBUF)           // 81920 B
#define QCHUNKS (HID / QBK)          // 32

__global__ __launch_bounds__(256)
void qkv_mma(const float* __restrict__ X,
             const float* __restrict__ Wq, const float* __restrict__ bq,
             const float* __restrict__ Wk, const float* __restrict__ bk,
             const float* __restrict__ Wv, const float* __restrict__ bv)
{
    extern __shared__ char sm[];
    const uint32_t sbase = smem_u32(sm);

    const int tid  = threadIdx.x;
    const int lane = tid & 31;
    const int wid  = tid >> 5;
    const int wm   = wid & 3;        // m group: rows wm*32..+31
    const int wn   = wid >> 2;       // n group: cols wn*64..+63

    const int m0   = blockIdx.x * 128;
    const int nb   = blockIdx.y;     // 0..23
    const int proj = nb >> 3;        // 0=q, 1=k, 2=v
    const int o0   = (nb & 7) * 128;

    const float* W    = (proj == 0) ? Wq : (proj == 1) ? Wk : Wv;
    const float* bias = (proj == 0) ? bq : (proj == 1) ? bk : bv;
    float*       dst  = (proj == 0) ? g_q : (proj == 1) ? g_k : g_v;

    float acc[2][8][4];
    #pragma unroll
    for (int mt = 0; mt < 2; mt++)
        #pragma unroll
        for (int nt = 0; nt < 8; nt++)
            #pragma unroll
            for (int r = 0; r < 4; r++) acc[mt][nt][r] = 0.f;

    // Per-thread global-load slots: 4 float4 for A, 4 for B per chunk.
    // f = i*256 + tid; row = f>>3 (0..127); c = (f&7)*4 floats.
    float4 stA[4], stB[4];
    const int ldRow = tid >> 3;            // base row for i=0
    const int ldC   = (tid & 7) << 2;      // float offset within chunk

    // ldmatrix lane addressing: row = lane&15, +16B col step for lane>=16.
    const uint32_t lmA = (uint32_t)((wm * 32 + (lane & 15)) * QROWB + (lane >> 4) * 16);
    const uint32_t lmB = (uint32_t)((wn * 64 + (lane & 15)) * QROWB + (lane >> 4) * 16);

    // ---- prologue: load + store chunk 0 ----
    #pragma unroll
    for (int i = 0; i < 4; i++) {
        int row = ldRow + i * 32;
        int gm  = m0 + row;
        stA[i] = (gm < NTOK) ? *(const float4*)(X + (size_t)gm * HID + ldC)
                             : make_float4(0.f, 0.f, 0.f, 0.f);
        stB[i] = *(const float4*)(W + (size_t)(o0 + row) * HID + ldC);
    }
    {
        char* Ah = sm;            char* Al = sm + QTILE;
        char* Bh = sm + 2*QTILE;  char* Bl = sm + 3*QTILE;
        #pragma unroll
        for (int i = 0; i < 4; i++) {
            uint32_t off = (uint32_t)((ldRow + i * 32) * QROWB + ldC * 2);
            split_sts(Ah, Al, off, stA[i]);
            split_sts(Bh, Bl, off, stB[i]);
        }
    }
    __syncthreads();

    for (int c = 0; c < QCHUNKS; c++) {
        // issue next chunk's global loads (overlap with mma below)
        if (c + 1 < QCHUNKS) {
            int kc = (c + 1) * QBK;
            #pragma unroll
            for (int i = 0; i < 4; i++) {
                int row = ldRow + i * 32;
                int gm  = m0 + row;
                stA[i] = (gm < NTOK) ? *(const float4*)(X + (size_t)gm * HID + kc + ldC)
                                     : make_float4(0.f, 0.f, 0.f, 0.f);
                stB[i] = *(const float4*)(W + (size_t)(o0 + row) * HID + kc + ldC);
            }
        }

        // ---- compute on buffer c&1 ----
        const uint32_t Ahb = sbase + (c & 1) * QBUF;
        const uint32_t Alb = Ahb + QTILE;
        const uint32_t Bhb = Ahb + 2 * QTILE;
        const uint32_t Blb = Ahb + 3 * QTILE;

        #pragma unroll
        for (int kk = 0; kk < 2; kk++) {           // two k16 steps per chunk
            const uint32_t kb = kk * 32;           // 16 bf16 = 32 bytes
            uint32_t fAh[2][4], fAl[2][4], fB[4][4];
            #pragma unroll
            for (int mt = 0; mt < 2; mt++) {
                LDMX4(fAh[mt], Ahb + lmA + mt * (16 * QROWB) + kb);
                LDMX4(fAl[mt], Alb + lmA + mt * (16 * QROWB) + kb);
            }
            #pragma unroll
            for (int n2 = 0; n2 < 4; n2++)
                LDMX4(fB[n2], Bhb + lmB + n2 * (16 * QROWB) + kb);
            #pragma unroll
            for (int mt = 0; mt < 2; mt++)
                #pragma unroll
                for (int nt = 0; nt < 8; nt++)     // hi * hi
                    MMA16816(acc[mt][nt], fAh[mt], fB[nt >> 1][nt & 1], fB[nt >> 1][2 + (nt & 1)]);
            #pragma unroll
            for (int mt = 0; mt < 2; mt++)
                #pragma unroll
                for (int nt = 0; nt < 8; nt++)     // lo * hi
                    MMA16816(acc[mt][nt], fAl[mt], fB[nt >> 1][nt & 1], fB[nt >> 1][2 + (nt & 1)]);
            #pragma unroll
            for (int n2 = 0; n2 < 4; n2++)
                LDMX4(fB[n2], Blb + lmB + n2 * (16 * QROWB) + kb);
            #pragma unroll
            for (int mt = 0; mt < 2; mt++)
                #pragma unroll
                for (int nt = 0; nt < 8; nt++)     // hi * lo
                    MMA16816(acc[mt][nt], fAh[mt], fB[nt >> 1][nt & 1], fB[nt >> 1][2 + (nt & 1)]);
        }

        // ---- store next chunk into the other buffer ----
        if (c + 1 < QCHUNKS) {
            char* Ah = sm + ((c + 1) & 1) * QBUF;
            char* Al = Ah + QTILE;
            char* Bh = Ah + 2 * QTILE;
            char* Bl = Ah + 3 * QTILE;
            #pragma unroll
            for (int i = 0; i < 4; i++) {
                uint32_t off = (uint32_t)((ldRow + i * 32) * QROWB + ldC * 2);
                split_sts(Ah, Al, off, stA[i]);
                split_sts(Bh, Bl, off, stB[i]);
            }
        }
        __syncthreads();
    }

    // ---- epilogue: bias add + scatter to [B, NH, L, HD] ----
    const int g   = lane >> 2;
    const int tig = lane & 3;
    const int headBase = (o0 + wn * 64) >> 6;     // one head per warp n-group
    #pragma unroll
    for (int mt = 0; mt < 2; mt++) {
        #pragma unroll
        for (int half = 0; half < 2; half++) {    // rows g and g+8
            int gm = m0 + wm * 32 + mt * 16 + g + half * 8;
            if (gm >= NTOK) continue;
            int bb = gm / SEQ;
            int ll = gm - bb * SEQ;
            float* dp = dst + (((size_t)bb * NH + headBase) * SEQ + ll) * HD;
            #pragma unroll
            for (int nt = 0; nt < 8; nt++) {
                int dd = nt * 8 + tig * 2;
                float2 bv = *(const float2*)(bias + o0 + wn * 64 + dd);
                float2 ov;
                ov.x = acc[mt][nt][half * 2 + 0] + bv.x;
                ov.y = acc[mt][nt][half * 2 + 1] + bv.y;
                *(float2*)(dp + dd) = ov;
            }
        }
    }
}

// ===========================================================================
// Phase 2: flash attention, fp32 SIMT. Padded linear smem layouts
// (affine LDS addressing -> immediate offsets, minimal ALU).
// ===========================================================================
#define BQ  64
#define BKV 64
#define FA_SMEM_TOTAL ((64*65*2 + 64*64) * 4)   // 49664 bytes

__global__ __launch_bounds__(256, 2)
void flash_attn(float* __restrict__ out)
{
    extern __shared__ float fsm[];
    float (*Qs)[65]  = reinterpret_cast<float(*)[65]>(fsm);
    float (*KPs)[65] = reinterpret_cast<float(*)[65]>(fsm + 64 * 65);
    float (*Vs)[64]  = reinterpret_cast<float(*)[64]>(fsm + 2 * 64 * 65);

    const int qt    = blockIdx.x;
    const int bh    = blockIdx.y;
    const int batch = bh >> 4;
    const int head  = bh & 15;
    const float* Q = g_q + (size_t)bh * SEQ * HD;
    const float* K = g_k + (size_t)bh * SEQ * HD;
    const float* V = g_v + (size_t)bh * SEQ * HD;
    const int q0 = qt * BQ;

    const int tid = threadIdx.x;
    const int tx  = tid & 15;
    const int ty  = tid >> 4;
    const int tx4 = tx * 4;
    const int ty4 = ty * 4;

    #pragma unroll
    for (int i = 0; i < 4; i++) {
        int f   = i * 256 + tid;
        int row = f >> 4;
        int c4  = (f & 15) << 2;
        int gq  = q0 + row;
        float4 v = (gq < SEQ)
            ? *(const float4*)(Q + (size_t)gq * HD + c4)
            : make_float4(0.f, 0.f, 0.f, 0.f);
        Qs[row][c4 + 0] = v.x; Qs[row][c4 + 1] = v.y;
        Qs[row][c4 + 2] = v.z; Qs[row][c4 + 3] = v.w;
    }

    float m_[4], l_[4], O[4][4];
    #pragma unroll
    for (int i = 0; i < 4; i++) {
        m_[i] = -1e30f;
        l_[i] = 0.f;
        #pragma unroll
        for (int j = 0; j < 4; j++) O[i][j] = 0.f;
    }

    for (int k0 = 0; k0 < SEQ; k0 += BKV) {
        __syncthreads();

        #pragma unroll
        for (int i = 0; i < 4; i++) {
            int f   = i * 256 + tid;
            int row = f >> 4;
            int c4  = (f & 15) << 2;
            int gk  = k0 + row;
            float4 vk, vv;
            if (gk < SEQ) {
                vk = *(const float4*)(K + (size_t)gk * HD + c4);
                vv = *(const float4*)(V + (size_t)gk * HD + c4);
            } else {
                vk = make_float4(0.f, 0.f, 0.f, 0.f);
                vv = vk;
            }
            KPs[row][c4 + 0] = vk.x; KPs[row][c4 + 1] = vk.y;
            KPs[row][c4 + 2] = vk.z; KPs[row][c4 + 3] = vk.w;
            *(float4*)(&Vs[row][c4]) = vv;
        }
        __syncthreads();

        float S[4][4];
        #pragma unroll
        for (int i = 0; i < 4; i++)
            #pragma unroll
            for (int j = 0; j < 4; j++) S[i][j] = 0.f;

        #pragma unroll 8
        for (int kd = 0; kd < 64; kd++) {
            float qa[4], kb[4];
            #pragma unroll
            for (int j = 0; j < 4; j++) {
                qa[j] = Qs [ty4 + j][kd];
                kb[j] = KPs[tx4 + j][kd];
            }
            #pragma unroll
            for (int i = 0; i < 4; i++)
                #pragma unroll
                for (int j = 0; j < 4; j++)
                    S[i][j] += qa[i] * kb[j];
        }

        #pragma unroll
        for (int i = 0; i < 4; i++)
            #pragma unroll
            for (int j = 0; j < 4; j++)
                S[i][j] *= 0.125f;

        if (k0 + BKV > SEQ) {
            #pragma unroll
            for (int i = 0; i < 4; i++)
                #pragma unroll
                for (int j = 0; j < 4; j++)
                    if (k0 + tx4 + j >= SEQ) S[i][j] = -1e30f;
        }

        #pragma unroll
        for (int i = 0; i < 4; i++) {
            float r = fmaxf(fmaxf(S[i][0], S[i][1]), fmaxf(S[i][2], S[i][3]));
            #pragma unroll
            for (int off = 8; off > 0; off >>= 1)
                r = fmaxf(r, __shfl_xor_sync(0xffffffffu, r, off));
            float mnew  = fmaxf(m_[i], r);
            float alpha = __expf(m_[i] - mnew);
            float rs = 0.f;
            #pragma unroll
            for (int j = 0; j < 4; j++) {
                float p = __expf(S[i][j] - mnew);
                S[i][j] = p;
                rs += p;
            }
            #pragma unroll
            for (int off = 8; off > 0; off >>= 1)
                rs += __shfl_xor_sync(0xffffffffu, rs, off);
            l_[i] = l_[i] * alpha + rs;
            m_[i] = mnew;
            #pragma unroll
            for (int j = 0; j < 4; j++) O[i][j] *= alpha;
        }

        __syncthreads();
        #pragma unroll
        for (int i = 0; i < 4; i++)
            #pragma unroll
            for (int j = 0; j < 4; j++)
                KPs[ty4 + i][tx4 + j] = S[i][j];
        __syncthreads();

        #pragma unroll 8
        for (int kc = 0; kc < 64; kc++) {
            float pa[4], vb[4];
            #pragma unroll
            for (int j = 0; j < 4; j++) {
                pa[j] = KPs[ty4 + j][kc];
                vb[j] = Vs [kc][tx4 + j];
            }
            #pragma unroll
            for (int i = 0; i < 4; i++)
                #pragma unroll
                for (int j = 0; j < 4; j++)
                    O[i][j] += pa[i] * vb[j];
        }
    }

    #pragma unroll
    for (int i = 0; i < 4; i++) {
        int gq = q0 + ty4 + i;
        if (gq >= SEQ) continue;
        float inv = 1.f / l_[i];
        #pragma unroll
        for (int j = 0; j < 4; j++) {
            out[((size_t)batch * SEQ + gq) * HID + head * HD + tx4 + j] =
                O[i][j] * inv;
        }
    }
}

// ---------------------------------------------------------------------------
// Launch
// ---------------------------------------------------------------------------
extern "C" void kernel_launch(void* const* d_in, const int* in_sizes, int n_in,
                              void* d_out, int out_size)
{
    const float* X  = (const float*)d_in[0];
    const float* Wq = (const float*)d_in[1];
    const float* bq = (const float*)d_in[2];
    const float* Wk = (const float*)d_in[3];
    const float* bk = (const float*)d_in[4];
    const float* Wv = (const float*)d_in[5];
    const float* bv = (const float*)d_in[6];
    float* out = (float*)d_out;

    cudaFuncSetAttribute(qkv_mma,    cudaFuncAttributeMaxDynamicSharedMemorySize, QK_SMEM);
    cudaFuncSetAttribute(flash_attn, cudaFuncAttributeMaxDynamicSharedMemorySize, FA_SMEM_TOTAL);

    dim3 g1((NTOK + 127) / 128, 24);                 // 43 x 24
    qkv_mma<<<g1, 256, QK_SMEM>>>(X, Wq, bq, Wk, bk, Wv, bv);

    dim3 g2((SEQ + BQ - 1) / BQ, BATCH * NH);        // 22 x 64
    flash_attn<<<g2, 256, FA_SMEM_TOTAL>>>(out);
}

// round 8
// speedup vs baseline: 3.6102x; 2.0338x over previous
#include <cuda_runtime.h>
#include <cuda_bf16.h>
#include <cstdint>

#define BATCH 4
#define SEQ   1370
#define NH    16
#define HD    64
#define HID   1024
#define NTOK  (BATCH * SEQ)   // 5480

// Scratch for projected Q/K/V in [B, NH, L, HD] layout.
__device__ float g_q[(size_t)BATCH * NH * SEQ * HD];
__device__ float g_k[(size_t)BATCH * NH * SEQ * HD];
__device__ float g_v[(size_t)BATCH * NH * SEQ * HD];

// ===========================================================================
// Helpers
// ===========================================================================
__device__ __forceinline__ uint32_t smem_u32(const void* p) {
    uint32_t a;
    asm("{ .reg .u64 t; cvta.to.shared.u64 t, %1; cvt.u32.u64 %0, t; }"
        : "=r"(a) : "l"(p));
    return a;
}

#define LDMX4(r, addr) \
    asm volatile("ldmatrix.sync.aligned.m8n8.x4.shared.b16 {%0,%1,%2,%3}, [%4];" \
        : "=r"((r)[0]), "=r"((r)[1]), "=r"((r)[2]), "=r"((r)[3]) : "r"(addr))

#define LDMX4T(r, addr) \
    asm volatile("ldmatrix.sync.aligned.m8n8.x4.trans.shared.b16 {%0,%1,%2,%3}, [%4];" \
        : "=r"((r)[0]), "=r"((r)[1]), "=r"((r)[2]), "=r"((r)[3]) : "r"(addr))

#define MMA16816(d, a, b0, b1) \
    asm volatile("mma.sync.aligned.m16n8k16.row.col.f32.bf16.bf16.f32 " \
        "{%0,%1,%2,%3}, {%4,%5,%6,%7}, {%8,%9}, {%0,%1,%2,%3};" \
        : "+f"((d)[0]), "+f"((d)[1]), "+f"((d)[2]), "+f"((d)[3]) \
        : "r"((a)[0]), "r"((a)[1]), "r"((a)[2]), "r"((a)[3]), "r"(b0), "r"(b1))

__device__ __forceinline__ uint32_t pack_bf16(float lo, float hi) {
    uint32_t r;
    asm("cvt.rn.bf16x2.f32 %0, %1, %2;" : "=r"(r) : "f"(hi), "f"(lo));
    return r;
}

// fp32 -> (bf16 hi, bf16 lo) split, 4 elements, stored as 8B in each plane.
__device__ __forceinline__ void split_sts(char* hp, char* lp, uint32_t off, float4 v) {
    __nv_bfloat16 h0 = __float2bfloat16_rn(v.x);
    __nv_bfloat16 h1 = __float2bfloat16_rn(v.y);
    __nv_bfloat16 h2 = __float2bfloat16_rn(v.z);
    __nv_bfloat16 h3 = __float2bfloat16_rn(v.w);
    float l0 = v.x - __bfloat162float(h0);
    float l1 = v.y - __bfloat162float(h1);
    float l2 = v.z - __bfloat162float(h2);
    float l3 = v.w - __bfloat162float(h3);
    __nv_bfloat162 hA = __halves2bfloat162(h0, h1);
    __nv_bfloat162 hB = __halves2bfloat162(h2, h3);
    uint32_t lA = pack_bf16(l0, l1);
    uint32_t lB = pack_bf16(l2, l3);
    *(uint2*)(hp + off) = make_uint2(*(uint32_t*)&hA, *(uint32_t*)&hB);
    *(uint2*)(lp + off) = make_uint2(lA, lB);
}

// ===========================================================================
// Phase 1: QKV projection on mma.sync (bf16 hi/lo split, fp32 accum).
// (unchanged from R7 — measured ~357us)
// ===========================================================================
#define QBK     32
#define QROWB   80
#define QTILE   (128 * QROWB)
#define QBUF    (4 * QTILE)
#define QK_SMEM (2 * QBUF)
#define QCHUNKS (HID / QBK)

__global__ __launch_bounds__(256)
void qkv_mma(const float* __restrict__ X,
             const float* __restrict__ Wq, const float* __restrict__ bq,
             const float* __restrict__ Wk, const float* __restrict__ bk,
             const float* __restrict__ Wv, const float* __restrict__ bv)
{
    extern __shared__ char sm[];
    const uint32_t sbase = smem_u32(sm);

    const int tid  = threadIdx.x;
    const int lane = tid & 31;
    const int wid  = tid >> 5;
    const int wm   = wid & 3;
    const int wn   = wid >> 2;

    const int m0   = blockIdx.x * 128;
    const int nb   = blockIdx.y;
    const int proj = nb >> 3;
    const int o0   = (nb & 7) * 128;

    const float* W    = (proj == 0) ? Wq : (proj == 1) ? Wk : Wv;
    const float* bias = (proj == 0) ? bq : (proj == 1) ? bk : bv;
    float*       dst  = (proj == 0) ? g_q : (proj == 1) ? g_k : g_v;

    float acc[2][8][4];
    #pragma unroll
    for (int mt = 0; mt < 2; mt++)
        #pragma unroll
        for (int nt = 0; nt < 8; nt++)
            #pragma unroll
            for (int r = 0; r < 4; r++) acc[mt][nt][r] = 0.f;

    float4 stA[4], stB[4];
    const int ldRow = tid >> 3;
    const int ldC   = (tid & 7) << 2;

    const uint32_t lmA = (uint32_t)((wm * 32 + (lane & 15)) * QROWB + (lane >> 4) * 16);
    const uint32_t lmB = (uint32_t)((wn * 64 + (lane & 15)) * QROWB + (lane >> 4) * 16);

    #pragma unroll
    for (int i = 0; i < 4; i++) {
        int row = ldRow + i * 32;
        int gm  = m0 + row;
        stA[i] = (gm < NTOK) ? *(const float4*)(X + (size_t)gm * HID + ldC)
                             : make_float4(0.f, 0.f, 0.f, 0.f);
        stB[i] = *(const float4*)(W + (size_t)(o0 + row) * HID + ldC);
    }
    {
        char* Ah = sm;            char* Al = sm + QTILE;
        char* Bh = sm + 2*QTILE;  char* Bl = sm + 3*QTILE;
        #pragma unroll
        for (int i = 0; i < 4; i++) {
            uint32_t off = (uint32_t)((ldRow + i * 32) * QROWB + ldC * 2);
            split_sts(Ah, Al, off, stA[i]);
            split_sts(Bh, Bl, off, stB[i]);
        }
    }
    __syncthreads();

    for (int c = 0; c < QCHUNKS; c++) {
        if (c + 1 < QCHUNKS) {
            int kc = (c + 1) * QBK;
            #pragma unroll
            for (int i = 0; i < 4; i++) {
                int row = ldRow + i * 32;
                int gm  = m0 + row;
                stA[i] = (gm < NTOK) ? *(const float4*)(X + (size_t)gm * HID + kc + ldC)
                                     : make_float4(0.f, 0.f, 0.f, 0.f);
                stB[i] = *(const float4*)(W + (size_t)(o0 + row) * HID + kc + ldC);
            }
        }

        const uint32_t Ahb = sbase + (c & 1) * QBUF;
        const uint32_t Alb = Ahb + QTILE;
        const uint32_t Bhb = Ahb + 2 * QTILE;
        const uint32_t Blb = Ahb + 3 * QTILE;

        #pragma unroll
        for (int kk = 0; kk < 2; kk++) {
            const uint32_t kb = kk * 32;
            uint32_t fAh[2][4], fAl[2][4], fB[4][4];
            #pragma unroll
            for (int mt = 0; mt < 2; mt++) {
                LDMX4(fAh[mt], Ahb + lmA + mt * (16 * QROWB) + kb);
                LDMX4(fAl[mt], Alb + lmA + mt * (16 * QROWB) + kb);
            }
            #pragma unroll
            for (int n2 = 0; n2 < 4; n2++)
                LDMX4(fB[n2], Bhb + lmB + n2 * (16 * QROWB) + kb);
            #pragma unroll
            for (int mt = 0; mt < 2; mt++)
                #pragma unroll
                for (int nt = 0; nt < 8; nt++)
                    MMA16816(acc[mt][nt], fAh[mt], fB[nt >> 1][nt & 1], fB[nt >> 1][2 + (nt & 1)]);
            #pragma unroll
            for (int mt = 0; mt < 2; mt++)
                #pragma unroll
                for (int nt = 0; nt < 8; nt++)
                    MMA16816(acc[mt][nt], fAl[mt], fB[nt >> 1][nt & 1], fB[nt >> 1][2 + (nt & 1)]);
            #pragma unroll
            for (int n2 = 0; n2 < 4; n2++)
                LDMX4(fB[n2], Blb + lmB + n2 * (16 * QROWB) + kb);
            #pragma unroll
            for (int mt = 0; mt < 2; mt++)
                #pragma unroll
                for (int nt = 0; nt < 8; nt++)
                    MMA16816(acc[mt][nt], fAh[mt], fB[nt >> 1][nt & 1], fB[nt >> 1][2 + (nt & 1)]);
        }

        if (c + 1 < QCHUNKS) {
            char* Ah = sm + ((c + 1) & 1) * QBUF;
            char* Al = Ah + QTILE;
            char* Bh = Ah + 2 * QTILE;
            char* Bl = Ah + 3 * QTILE;
            #pragma unroll
            for (int i = 0; i < 4; i++) {
                uint32_t off = (uint32_t)((ldRow + i * 32) * QROWB + ldC * 2);
                split_sts(Ah, Al, off, stA[i]);
                split_sts(Bh, Bl, off, stB[i]);
            }
        }
        __syncthreads();
    }

    const int g   = lane >> 2;
    const int tig = lane & 3;
    const int headBase = (o0 + wn * 64) >> 6;
    #pragma unroll
    for (int mt = 0; mt < 2; mt++) {
        #pragma unroll
        for (int half = 0; half < 2; half++) {
            int gm = m0 + wm * 32 + mt * 16 + g + half * 8;
            if (gm >= NTOK) continue;
            int bb = gm / SEQ;
            int ll = gm - bb * SEQ;
            float* dp = dst + (((size_t)bb * NH + headBase) * SEQ + ll) * HD;
            #pragma unroll
            for (int nt = 0; nt < 8; nt++) {
                int dd = nt * 8 + tig * 2;
                float2 bv = *(const float2*)(bias + o0 + wn * 64 + dd);
                float2 ov;
                ov.x = acc[mt][nt][half * 2 + 0] + bv.x;
                ov.y = acc[mt][nt][half * 2 + 1] + bv.y;
                *(float2*)(dp + dd) = ov;
            }
        }
    }
}

// ===========================================================================
// Phase 2: flash attention on mma.sync (bf16 hi/lo split, fp32 accum).
// Block = 128 q rows x 8 warps (warp = m16 x all 64 kv / 64 d), BKV = 64.
// S = Qh*Kh + Qh*Kl + Ql*Kh ; O = Ph*Vh + Ph*Vl + Pl*Vh (P register-only).
// Smem rows padded to 144B -> conflict-free ldmatrix.
// ===========================================================================
#define FROWB 144                 // 64 bf16 data + 8 bf16 pad = 144 bytes
#define FA_QH 0
#define FA_QL (128 * FROWB)                 // 18432
#define FA_KH (2 * 128 * FROWB)             // 36864
#define FA_KL (FA_KH + 64 * FROWB)          // 46080
#define FA_VH (FA_KL + 64 * FROWB)          // 55296
#define FA_VL (FA_VH + 64 * FROWB)          // 64512
#define FA_SMEM (FA_VL + 64 * FROWB)        // 73728

__global__ __launch_bounds__(256)
void flash_mma(float* __restrict__ out)
{
    extern __shared__ char sm[];
    const uint32_t sb = smem_u32(sm);

    const int tid  = threadIdx.x;
    const int lane = tid & 31;
    const int w    = tid >> 5;

    const int qt    = blockIdx.x;       // 0..10
    const int bh    = blockIdx.y;       // 0..63
    const int batch = bh >> 4;
    const int head  = bh & 15;
    const float* Q = g_q + (size_t)bh * SEQ * HD;
    const float* K = g_k + (size_t)bh * SEQ * HD;
    const float* V = g_v + (size_t)bh * SEQ * HD;
    const int q0 = qt * 128;

    // Load Q tile, pre-scaled by 1/sqrt(64)=0.125 (exact pow2, before split).
    #pragma unroll
    for (int i = 0; i < 8; i++) {
        int f   = i * 256 + tid;
        int row = f >> 4;
        int c4  = (f & 15) << 2;
        int gq  = q0 + row;
        float4 v = (gq < SEQ)
            ? *(const float4*)(Q + (size_t)gq * HD + c4)
            : make_float4(0.f, 0.f, 0.f, 0.f);
        v.x *= 0.125f; v.y *= 0.125f; v.z *= 0.125f; v.w *= 0.125f;
        split_sts(sm + FA_QH, sm + FA_QL, (uint32_t)(row * FROWB + c4 * 2), v);
    }

    const uint32_t lmQ  = (uint32_t)((w * 16 + (lane & 15)) * FROWB + (lane >> 4) * 16);
    const uint32_t lmKV = (uint32_t)((lane & 15) * FROWB + (lane >> 4) * 16);
    const int g   = lane >> 2;
    const int tig = lane & 3;

    float m0v = -1e30f, m1v = -1e30f, l0v = 0.f, l1v = 0.f;
    float O[8][4];
    #pragma unroll
    for (int nt = 0; nt < 8; nt++)
        #pragma unroll
        for (int r = 0; r < 4; r++) O[nt][r] = 0.f;

    for (int kv0 = 0; kv0 < SEQ; kv0 += 64) {
        __syncthreads();   // prior tile's ldmatrix done (also orders Q stores, iter 0)

        // Load K, V tiles (64 x 64 fp32 each), split to bf16 hi/lo.
        #pragma unroll
        for (int i = 0; i < 4; i++) {
            int f   = i * 256 + tid;
            int row = f >> 4;
            int c4  = (f & 15) << 2;
            int gk  = kv0 + row;
            float4 vk, vv;
            if (gk < SEQ) {
                vk = *(const float4*)(K + (size_t)gk * HD + c4);
                vv = *(const float4*)(V + (size_t)gk * HD + c4);
            } else {
                vk = make_float4(0.f, 0.f, 0.f, 0.f);
                vv = vk;
            }
            uint32_t off = (uint32_t)(row * FROWB + c4 * 2);
            split_sts(sm + FA_KH, sm + FA_KL, off, vk);
            split_sts(sm + FA_VH, sm + FA_VL, off, vv);
        }
        __syncthreads();

        // ---- S = Q @ K^T (3-term split) ----
        float S[8][4];
        #pragma unroll
        for (int nt = 0; nt < 8; nt++)
            #pragma unroll
            for (int r = 0; r < 4; r++) S[nt][r] = 0.f;

        #pragma unroll
        for (int ks = 0; ks < 4; ks++) {
            uint32_t qh[4], ql[4];
            LDMX4(qh, sb + FA_QH + lmQ + ks * 32);
            LDMX4(ql, sb + FA_QL + lmQ + ks * 32);
            #pragma unroll
            for (int n16 = 0; n16 < 4; n16++) {
                uint32_t kh[4], kl[4];
                LDMX4(kh, sb + FA_KH + lmKV + n16 * (16 * FROWB) + ks * 32);
                LDMX4(kl, sb + FA_KL + lmKV + n16 * (16 * FROWB) + ks * 32);
                MMA16816(S[2*n16],   qh, kh[0], kh[2]);
                MMA16816(S[2*n16+1], qh, kh[1], kh[3]);
                MMA16816(S[2*n16],   qh, kl[0], kl[2]);
                MMA16816(S[2*n16+1], qh, kl[1], kl[3]);
                MMA16816(S[2*n16],   ql, kh[0], kh[2]);
                MMA16816(S[2*n16+1], ql, kh[1], kh[3]);
            }
        }

        // ---- key mask (last tile only) ----
        if (kv0 + 64 > SEQ) {
            #pragma unroll
            for (int nt = 0; nt < 8; nt++)
                #pragma unroll
                for (int e = 0; e < 4; e++)
                    if (kv0 + nt * 8 + tig * 2 + (e & 1) >= SEQ) S[nt][e] = -1e30f;
        }

        // ---- online softmax (rows g and g+8; quad = lanes sharing g) ----
        float mx0 = -1e30f, mx1 = -1e30f;
        #pragma unroll
        for (int nt = 0; nt < 8; nt++) {
            mx0 = fmaxf(mx0, fmaxf(S[nt][0], S[nt][1]));
            mx1 = fmaxf(mx1, fmaxf(S[nt][2], S[nt][3]));
        }
        #pragma unroll
        for (int off = 1; off <= 2; off <<= 1) {
            mx0 = fmaxf(mx0, __shfl_xor_sync(0xffffffffu, mx0, off));
            mx1 = fmaxf(mx1, __shfl_xor_sync(0xffffffffu, mx1, off));
        }
        float mnew0 = fmaxf(m0v, mx0);
        float mnew1 = fmaxf(m1v, mx1);
        float a0 = __expf(m0v - mnew0);
        float a1 = __expf(m1v - mnew1);
        m0v = mnew0; m1v = mnew1;

        uint32_t Ph[8][2], Pl[8][2];
        float rs0 = 0.f, rs1 = 0.f;
        #pragma unroll
        for (int nt = 0; nt < 8; nt++) {
            float p0 = __expf(S[nt][0] - mnew0);
            float p1 = __expf(S[nt][1] - mnew0);
            float p2 = __expf(S[nt][2] - mnew1);
            float p3 = __expf(S[nt][3] - mnew1);
            rs0 += p0 + p1;
            rs1 += p2 + p3;
            __nv_bfloat16 h0 = __float2bfloat16_rn(p0);
            __nv_bfloat16 h1 = __float2bfloat16_rn(p1);
            __nv_bfloat16 h2 = __float2bfloat16_rn(p2);
            __nv_bfloat16 h3 = __float2bfloat16_rn(p3);
            __nv_bfloat162 hA = __halves2bfloat162(h0, h1);
            __nv_bfloat162 hB = __halves2bfloat162(h2, h3);
            Ph[nt][0] = *(uint32_t*)&hA;
            Ph[nt][1] = *(uint32_t*)&hB;
            Pl[nt][0] = pack_bf16(p0 - __bfloat162float(h0), p1 - __bfloat162float(h1));
            Pl[nt][1] = pack_bf16(p2 - __bfloat162float(h2), p3 - __bfloat162float(h3));
        }
        #pragma unroll
        for (int off = 1; off <= 2; off <<= 1) {
            rs0 += __shfl_xor_sync(0xffffffffu, rs0, off);
            rs1 += __shfl_xor_sync(0xffffffffu, rs1, off);
        }
        l0v = l0v * a0 + rs0;
        l1v = l1v * a1 + rs1;
        #pragma unroll
        for (int nt = 0; nt < 8; nt++) {
            O[nt][0] *= a0; O[nt][1] *= a0;
            O[nt][2] *= a1; O[nt][3] *= a1;
        }

        // ---- O += P @ V (3-term split; P from registers, V via ldmatrix.trans) ----
        #pragma unroll
        for (int ks = 0; ks < 4; ks++) {
            uint32_t aH[4] = {Ph[2*ks][0], Ph[2*ks][1], Ph[2*ks+1][0], Ph[2*ks+1][1]};
            uint32_t aL[4] = {Pl[2*ks][0], Pl[2*ks][1], Pl[2*ks+1][0], Pl[2*ks+1][1]};
            #pragma unroll
            for (int d16 = 0; d16 < 4; d16++) {
                uint32_t vh[4], vl[4];
                LDMX4T(vh, sb + FA_VH + lmKV + ks * (16 * FROWB) + d16 * 32);
                LDMX4T(vl, sb + FA_VL + lmKV + ks * (16 * FROWB) + d16 * 32);
                MMA16816(O[2*d16],   aH, vh[0], vh[1]);
                MMA16816(O[2*d16+1], aH, vh[2], vh[3]);
                MMA16816(O[2*d16],   aH, vl[0], vl[1]);
                MMA16816(O[2*d16+1], aH, vl[2], vl[3]);
                MMA16816(O[2*d16],   aL, vh[0], vh[1]);
                MMA16816(O[2*d16+1], aL, vh[2], vh[3]);
            }
        }
    }

    // ---- epilogue: normalize and write ctx[b, l, head*64 + d] ----
    const float inv0 = 1.f / l0v;
    const float inv1 = 1.f / l1v;
    const int r0 = q0 + w * 16 + g;
    const int r1 = r0 + 8;
    #pragma unroll
    for (int nt = 0; nt < 8; nt++) {
        int dd = head * HD + nt * 8 + tig * 2;
        if (r0 < SEQ) {
            float2 o = make_float2(O[nt][0] * inv0, O[nt][1] * inv0);
            *(float2*)(out + ((size_t)batch * SEQ + r0) * HID + dd) = o;
        }
        if (r1 < SEQ) {
            float2 o = make_float2(O[nt][2] * inv1, O[nt][3] * inv1);
            *(float2*)(out + ((size_t)batch * SEQ + r1) * HID + dd) = o;
        }
    }
}

// ---------------------------------------------------------------------------
// Launch
// ---------------------------------------------------------------------------
extern "C" void kernel_launch(void* const* d_in, const int* in_sizes, int n_in,
                              void* d_out, int out_size)
{
    const float* X  = (const float*)d_in[0];
    const float* Wq = (const float*)d_in[1];
    const float* bq = (const float*)d_in[2];
    const float* Wk = (const float*)d_in[3];
    const float* bk = (const float*)d_in[4];
    const float* Wv = (const float*)d_in[5];
    const float* bv = (const float*)d_in[6];
    float* out = (float*)d_out;

    cudaFuncSetAttribute(qkv_mma,   cudaFuncAttributeMaxDynamicSharedMemorySize, QK_SMEM);
    cudaFuncSetAttribute(flash_mma, cudaFuncAttributeMaxDynamicSharedMemorySize, FA_SMEM);

    dim3 g1((NTOK + 127) / 128, 24);                 // 43 x 24
    qkv_mma<<<g1, 256, QK_SMEM>>>(X, Wq, bq, Wk, bk, Wv, bv);

    dim3 g2((SEQ + 127) / 128, BATCH * NH);          // 11 x 64
    flash_mma<<<g2, 256, FA_SMEM>>>(out);
}